// round 2
// baseline (speedup 1.0000x reference)
#include <cuda_runtime.h>
#include <cuda_bf16.h>
#include <cstdint>

// Problem constants (fixed shapes per reference)
#define MAXN 50000
#define MAXE 800000
#define MAXF 128

// ---------------- device scratch (allocation-free) ----------------
__device__ int   g_cnt_src[MAXN];
__device__ int   g_cnt_dst[MAXN];
__device__ float g_norm_src[MAXN];
__device__ float g_norm_dst[MAXN];
__device__ int   g_rowptr[MAXN + 1];
__device__ int   g_cursor[MAXN];
__device__ int   g_esrc[MAXE];
__device__ float g_t[(size_t)MAXN * MAXF];   // transformed features (h @ W) * norm_src
__device__ float g_h[(size_t)MAXN * MAXF];   // layer activations

// ---------------- degree histograms ----------------
__global__ void degree_kernel(const int* __restrict__ src, const int* __restrict__ dst, int E) {
    int e = blockIdx.x * blockDim.x + threadIdx.x;
    if (e < E) {
        atomicAdd(&g_cnt_src[src[e]], 1);
        atomicAdd(&g_cnt_dst[dst[e]], 1);
    }
}

__global__ void norm_kernel(int Nn) {
    int i = blockIdx.x * blockDim.x + threadIdx.x;
    if (i < Nn) {
        int cs = g_cnt_src[i]; if (cs < 1) cs = 1;
        int cd = g_cnt_dst[i]; if (cd < 1) cd = 1;
        g_norm_src[i] = rsqrtf((float)cs);
        g_norm_dst[i] = rsqrtf((float)cd);
    }
}

// ---------------- single-block exclusive scan over in-degree counts ----------------
__global__ void scan_kernel(int Nn) {
    __shared__ int wsum[32];
    __shared__ int s_carry;
    int lane = threadIdx.x & 31;
    int wid  = threadIdx.x >> 5;
    if (threadIdx.x == 0) { s_carry = 0; g_rowptr[0] = 0; }
    __syncthreads();
    for (int base = 0; base < Nn; base += 1024) {
        int i = base + (int)threadIdx.x;
        int v = (i < Nn) ? g_cnt_dst[i] : 0;
        int xv = v;
        #pragma unroll
        for (int off = 1; off < 32; off <<= 1) {
            int y = __shfl_up_sync(0xffffffffu, xv, off);
            if (lane >= off) xv += y;
        }
        if (lane == 31) wsum[wid] = xv;
        __syncthreads();
        if (wid == 0) {
            int w = wsum[lane];
            #pragma unroll
            for (int off = 1; off < 32; off <<= 1) {
                int y = __shfl_up_sync(0xffffffffu, w, off);
                if (lane >= off) w += y;
            }
            wsum[lane] = w;
        }
        __syncthreads();
        int incl = s_carry + xv + (wid ? wsum[wid - 1] : 0);
        if (i < Nn) g_rowptr[i + 1] = incl;
        __syncthreads();
        if (threadIdx.x == 1023) s_carry = incl;
        __syncthreads();
    }
}

// ---------------- bin edges by destination (CSR build) ----------------
__global__ void bin_kernel(const int* __restrict__ src, const int* __restrict__ dst, int E) {
    int e = blockIdx.x * blockDim.x + threadIdx.x;
    if (e < E) {
        int p = atomicAdd(&g_cursor[dst[e]], 1);
        g_esrc[p] = src[e];
    }
}

// ---------------- register-tiled GEMM: Cout[n,:] = (A[n,:] @ W) * norm_src[n] ----------------
template <int DIN, int DOUT>
__global__ void __launch_bounds__(256) gemm_kernel(const float* __restrict__ A,
                                                   const float* __restrict__ W,
                                                   float* __restrict__ Cout, int Nn) {
    constexpr int BM = 64;
    constexpr int BN = (DOUT < 64) ? DOUT : 64;
    constexpr int BK = 16;
    constexpr int TM = 4;
    constexpr int TN = BN / 16;           // 4, 2, or 1

    __shared__ float sA[BK][BM + 4];      // A transposed: sA[k][row]
    __shared__ float sB[BK][BN];

    int row0 = blockIdx.x * BM;
    int col0 = blockIdx.y * BN;
    int tx = threadIdx.x % 16;            // column group
    int ty = threadIdx.x / 16;            // row group

    float acc[TM][TN];
    #pragma unroll
    for (int i = 0; i < TM; i++)
        #pragma unroll
        for (int j = 0; j < TN; j++) acc[i][j] = 0.f;

    for (int k0 = 0; k0 < DIN; k0 += BK) {
        // load A tile (coalesced along k), store transposed
        #pragma unroll
        for (int idx = threadIdx.x; idx < BM * BK; idx += 256) {
            int c = idx % BK, r = idx / BK;
            int gr = row0 + r;
            sA[c][r] = (gr < Nn) ? A[(size_t)gr * DIN + k0 + c] : 0.f;
        }
        // load B tile (coalesced along n)
        #pragma unroll
        for (int idx = threadIdx.x; idx < BK * BN; idx += 256) {
            int c = idx % BN, r = idx / BN;
            sB[r][c] = W[(k0 + r) * DOUT + col0 + c];
        }
        __syncthreads();
        #pragma unroll
        for (int kk = 0; kk < BK; kk++) {
            float a[TM], bb[TN];
            #pragma unroll
            for (int i = 0; i < TM; i++) a[i] = sA[kk][ty * TM + i];
            #pragma unroll
            for (int j = 0; j < TN; j++) bb[j] = sB[kk][tx * TN + j];
            #pragma unroll
            for (int i = 0; i < TM; i++)
                #pragma unroll
                for (int j = 0; j < TN; j++)
                    acc[i][j] += a[i] * bb[j];
        }
        __syncthreads();
    }
    #pragma unroll
    for (int i = 0; i < TM; i++) {
        int gr = row0 + ty * TM + i;
        if (gr < Nn) {
            float ns = g_norm_src[gr];
            #pragma unroll
            for (int j = 0; j < TN; j++)
                Cout[(size_t)gr * DOUT + col0 + tx * TN + j] = acc[i][j] * ns;
        }
    }
}

// ---------------- CSR gather + norm_dst + bias + relu (fused epilogue) ----------------
template <int D>
__global__ void __launch_bounds__(256) gather_kernel(const float* __restrict__ t,
                                                     const float* __restrict__ bias,
                                                     float* __restrict__ out, int Nn) {
    int n = blockIdx.x * blockDim.y + threadIdx.y;
    if (n >= Nn) return;
    int f = threadIdx.x;
    int beg = g_rowptr[n], end = g_rowptr[n + 1];
    float acc = 0.f;
    int j = beg;
    for (; j + 4 <= end; j += 4) {           // 4-deep MLP through L2
        int s0 = g_esrc[j], s1 = g_esrc[j + 1], s2 = g_esrc[j + 2], s3 = g_esrc[j + 3];
        float v0 = t[s0 * D + f];
        float v1 = t[s1 * D + f];
        float v2 = t[s2 * D + f];
        float v3 = t[s3 * D + f];
        acc += (v0 + v1) + (v2 + v3);
    }
    for (; j < end; j++) acc += t[g_esrc[j] * D + f];
    out[(size_t)n * D + f] = fmaxf(fmaf(acc, g_norm_dst[n], bias[f]), 0.f);
}

// ---------------- launch ----------------
extern "C" void kernel_launch(void* const* d_in, const int* in_sizes, int n_in,
                              void* d_out, int out_size) {
    const float* x  = (const float*)d_in[0];
    const int*   ed = (const int*)d_in[1];
    const float* W1 = (const float*)d_in[2];   const float* b1 = (const float*)d_in[3];
    const float* W2 = (const float*)d_in[4];   const float* b2 = (const float*)d_in[5];
    const float* W3 = (const float*)d_in[6];   const float* b3 = (const float*)d_in[7];
    const float* W4 = (const float*)d_in[8];   const float* b4 = (const float*)d_in[9];
    const float* W5 = (const float*)d_in[10];  const float* b5 = (const float*)d_in[11];

    const int Nn = in_sizes[0] / 128;
    const int E  = in_sizes[1] / 2;
    const int* src = ed;
    const int* dst = ed + E;

    void *pcs = nullptr, *pcd = nullptr, *prp = nullptr, *pcur = nullptr, *pt = nullptr, *ph = nullptr;
    cudaGetSymbolAddress(&pcs,  g_cnt_src);
    cudaGetSymbolAddress(&pcd,  g_cnt_dst);
    cudaGetSymbolAddress(&prp,  g_rowptr);
    cudaGetSymbolAddress(&pcur, g_cursor);
    cudaGetSymbolAddress(&pt,   g_t);
    cudaGetSymbolAddress(&ph,   g_h);
    float* t = (float*)pt;
    float* h = (float*)ph;

    cudaMemsetAsync(pcs, 0, Nn * sizeof(int), 0);
    cudaMemsetAsync(pcd, 0, Nn * sizeof(int), 0);

    int eb = (E + 255) / 256;
    degree_kernel<<<eb, 256>>>(src, dst, E);
    norm_kernel<<<(Nn + 255) / 256, 256>>>(Nn);
    scan_kernel<<<1, 1024>>>(Nn);
    cudaMemcpyAsync(pcur, prp, Nn * sizeof(int), cudaMemcpyDeviceToDevice, 0);
    bin_kernel<<<eb, 256>>>(src, dst, E);

    // Layer 1: 128 -> 128
    gemm_kernel<128, 128><<<dim3((Nn + 63) / 64, 2), 256>>>(x, W1, t, Nn);
    gather_kernel<128><<<(Nn + 1) / 2, dim3(128, 2)>>>(t, b1, h, Nn);
    // Layer 2: 128 -> 64
    gemm_kernel<128, 64><<<dim3((Nn + 63) / 64, 1), 256>>>(h, W2, t, Nn);
    gather_kernel<64><<<(Nn + 3) / 4, dim3(64, 4)>>>(t, b2, h, Nn);
    // Layer 3: 64 -> 32
    gemm_kernel<64, 32><<<dim3((Nn + 63) / 64, 1), 256>>>(h, W3, t, Nn);
    gather_kernel<32><<<(Nn + 7) / 8, dim3(32, 8)>>>(t, b3, h, Nn);
    // Layer 4: 32 -> 16
    gemm_kernel<32, 16><<<dim3((Nn + 63) / 64, 1), 256>>>(h, W4, t, Nn);
    gather_kernel<16><<<(Nn + 15) / 16, dim3(16, 16)>>>(t, b4, h, Nn);
    // Layer 5: 16 -> 16
    gemm_kernel<16, 16><<<dim3((Nn + 63) / 64, 1), 256>>>(h, W5, t, Nn);
    gather_kernel<16><<<(Nn + 15) / 16, dim3(16, 16)>>>(t, b5, (float*)d_out, Nn);
}

// round 3
// speedup vs baseline: 1.2461x; 1.2461x over previous
#include <cuda_runtime.h>
#include <cuda_bf16.h>
#include <cstdint>

#define MAXN 50000
#define MAXE 800000
#define MAXF 128

typedef unsigned long long u64;

// ---------------- device scratch (allocation-free) ----------------
__device__ int   g_cnt_src[MAXN];
__device__ int   g_cnt_dst[MAXN];
__device__ float g_norm_src[MAXN];
__device__ float g_norm_dst[MAXN];
__device__ int   g_rowptr[MAXN + 1];
__device__ int   g_cursor[MAXN];
__device__ int   g_esrc[MAXE];
__device__ float g_t[(size_t)MAXN * MAXF];
__device__ float g_h[(size_t)MAXN * MAXF];

// ---------------- f32x2 packed math helpers ----------------
__device__ __forceinline__ u64 dup2(float v) {
    u64 r; asm("mov.b64 %0, {%1, %1};" : "=l"(r) : "f"(v)); return r;
}
__device__ __forceinline__ void fma2(u64& d, u64 a, u64 b) {
    asm("fma.rn.f32x2 %0, %1, %2, %0;" : "+l"(d) : "l"(a), "l"(b));
}
__device__ __forceinline__ void unpack2(u64 v, float& lo, float& hi) {
    asm("mov.b64 {%0, %1}, %2;" : "=f"(lo), "=f"(hi) : "l"(v));
}

// ---------------- degree histograms (4 edges / thread, int4 loads) ----------------
__global__ void degree_kernel(const int* __restrict__ src, const int* __restrict__ dst, int E) {
    int e0 = (blockIdx.x * blockDim.x + threadIdx.x) * 4;
    if (e0 + 3 < E) {
        int4 s = *(const int4*)&src[e0];
        int4 d = *(const int4*)&dst[e0];
        atomicAdd(&g_cnt_src[s.x], 1); atomicAdd(&g_cnt_src[s.y], 1);
        atomicAdd(&g_cnt_src[s.z], 1); atomicAdd(&g_cnt_src[s.w], 1);
        atomicAdd(&g_cnt_dst[d.x], 1); atomicAdd(&g_cnt_dst[d.y], 1);
        atomicAdd(&g_cnt_dst[d.z], 1); atomicAdd(&g_cnt_dst[d.w], 1);
    } else {
        for (int e = e0; e < E; e++) {
            atomicAdd(&g_cnt_src[src[e]], 1);
            atomicAdd(&g_cnt_dst[dst[e]], 1);
        }
    }
}

// ---------------- scan over in-degree + norms + cursor init (fused) ----------------
__global__ void scan_kernel(int Nn) {
    __shared__ int wsum[32];
    __shared__ int s_carry;
    int lane = threadIdx.x & 31;
    int wid  = threadIdx.x >> 5;
    if (threadIdx.x == 0) { s_carry = 0; g_rowptr[0] = 0; }
    __syncthreads();
    for (int base = 0; base < Nn; base += 1024) {
        int i = base + (int)threadIdx.x;
        int v = (i < Nn) ? g_cnt_dst[i] : 0;
        int xv = v;
        #pragma unroll
        for (int off = 1; off < 32; off <<= 1) {
            int y = __shfl_up_sync(0xffffffffu, xv, off);
            if (lane >= off) xv += y;
        }
        if (lane == 31) wsum[wid] = xv;
        __syncthreads();
        if (wid == 0) {
            int w = wsum[lane];
            #pragma unroll
            for (int off = 1; off < 32; off <<= 1) {
                int y = __shfl_up_sync(0xffffffffu, w, off);
                if (lane >= off) w += y;
            }
            wsum[lane] = w;
        }
        __syncthreads();
        int incl = s_carry + xv + (wid ? wsum[wid - 1] : 0);
        if (i < Nn) {
            g_rowptr[i + 1] = incl;
            g_cursor[i] = incl - v;                 // exclusive prefix = row start
            int cs = g_cnt_src[i]; if (cs < 1) cs = 1;
            int cd = v;            if (cd < 1) cd = 1;
            g_norm_src[i] = rsqrtf((float)cs);
            g_norm_dst[i] = rsqrtf((float)cd);
        }
        __syncthreads();
        if (threadIdx.x == 1023) s_carry = incl;
        __syncthreads();
    }
}

// ---------------- bin edges by destination (4 edges / thread) ----------------
__global__ void bin_kernel(const int* __restrict__ src, const int* __restrict__ dst, int E) {
    int e0 = (blockIdx.x * blockDim.x + threadIdx.x) * 4;
    if (e0 + 3 < E) {
        int4 s = *(const int4*)&src[e0];
        int4 d = *(const int4*)&dst[e0];
        int p0 = atomicAdd(&g_cursor[d.x], 1);
        int p1 = atomicAdd(&g_cursor[d.y], 1);
        int p2 = atomicAdd(&g_cursor[d.z], 1);
        int p3 = atomicAdd(&g_cursor[d.w], 1);
        g_esrc[p0] = s.x; g_esrc[p1] = s.y; g_esrc[p2] = s.z; g_esrc[p3] = s.w;
    } else {
        for (int e = e0; e < E; e++) {
            int p = atomicAdd(&g_cursor[dst[e]], 1);
            g_esrc[p] = src[e];
        }
    }
}

// ------- GEMM: Cout[n,:] = (A[n,:] @ W) * norm_src[n], f32x2 packed FFMA -------
template <int DIN, int DOUT>
__global__ void __launch_bounds__(256) gemm_kernel(const float* __restrict__ A,
                                                   const float* __restrict__ W,
                                                   float* __restrict__ Cout, int Nn) {
    constexpr int BM = 128;
    constexpr int BN = (DOUT < 64) ? DOUT : 64;
    constexpr int BK = 16;
    constexpr int TN = 4;
    constexpr int TXC = BN / TN;          // 4, 8, 16
    constexpr int TYC = 256 / TXC;        // 64, 32, 16
    constexpr int TM = BM / TYC;          // 2, 4, 8
    constexpr int TP = TM / 2;            // M-pairs

    __shared__ float sA[BK][BM + 4];      // transposed, row stride 132 floats (16B-aligned)
    __shared__ float sB[BK][BN];

    int row0 = blockIdx.x * BM;
    int col0 = blockIdx.y * BN;
    int tx = threadIdx.x % TXC;
    int ty = threadIdx.x / TXC;

    u64 acc[TP][TN];
    #pragma unroll
    for (int p = 0; p < TP; p++)
        #pragma unroll
        for (int j = 0; j < TN; j++) acc[p][j] = 0ull;   // bit pattern (0.f, 0.f)

    for (int k0 = 0; k0 < DIN; k0 += BK) {
        // A tile: float4 global loads, transposed scatter into sA
        #pragma unroll
        for (int idx = threadIdx.x; idx < BM * BK / 4; idx += 256) {
            int r = idx / (BK / 4);
            int c4 = (idx % (BK / 4)) * 4;
            int gr = row0 + r;
            float4 v = make_float4(0.f, 0.f, 0.f, 0.f);
            if (gr < Nn) v = *(const float4*)&A[(size_t)gr * DIN + k0 + c4];
            sA[c4 + 0][r] = v.x; sA[c4 + 1][r] = v.y;
            sA[c4 + 2][r] = v.z; sA[c4 + 3][r] = v.w;
        }
        // B tile: float4 loads
        #pragma unroll
        for (int idx = threadIdx.x; idx < BK * BN / 4; idx += 256) {
            int r = idx / (BN / 4);
            int c4 = (idx % (BN / 4)) * 4;
            *(float4*)&sB[r][c4] = *(const float4*)&W[(k0 + r) * DOUT + col0 + c4];
        }
        __syncthreads();
        #pragma unroll
        for (int kk = 0; kk < BK; kk++) {
            u64 a2[TP];
            #pragma unroll
            for (int p = 0; p < TP; p++)
                a2[p] = *(const u64*)&sA[kk][ty * TM + 2 * p];   // (row m, row m+1)
            u64 b2[TN];
            #pragma unroll
            for (int j = 0; j < TN; j++)
                b2[j] = dup2(sB[kk][tx * TN + j]);
            #pragma unroll
            for (int p = 0; p < TP; p++)
                #pragma unroll
                for (int j = 0; j < TN; j++)
                    fma2(acc[p][j], a2[p], b2[j]);
        }
        __syncthreads();
    }
    // epilogue: unpack pairs, scale by norm_src, float4 stores
    #pragma unroll
    for (int p = 0; p < TP; p++) {
        float lo[TN], hi[TN];
        #pragma unroll
        for (int j = 0; j < TN; j++) unpack2(acc[p][j], lo[j], hi[j]);
        int gr = row0 + ty * TM + 2 * p;
        if (gr < Nn) {
            float ns = g_norm_src[gr];
            float4 o = make_float4(lo[0] * ns, lo[1] * ns, lo[2] * ns, lo[3] * ns);
            *(float4*)&Cout[(size_t)gr * DOUT + col0 + tx * TN] = o;
        }
        if (gr + 1 < Nn) {
            float ns = g_norm_src[gr + 1];
            float4 o = make_float4(hi[0] * ns, hi[1] * ns, hi[2] * ns, hi[3] * ns);
            *(float4*)&Cout[(size_t)(gr + 1) * DOUT + col0 + tx * TN] = o;
        }
    }
}

// ------- CSR gather + norm_dst + bias + relu, float4 per thread -------
template <int D>
__global__ void __launch_bounds__(256) gather_kernel(const float* __restrict__ t,
                                                     const float* __restrict__ bias,
                                                     float* __restrict__ out, int Nn) {
    constexpr int TX = D / 4;             // float4 lanes per node: 32,16,8,4
    int n = blockIdx.x * blockDim.y + threadIdx.y;
    if (n >= Nn) return;
    int f = threadIdx.x;
    const float4* t4 = (const float4*)t;
    int beg = g_rowptr[n], end = g_rowptr[n + 1];
    float4 acc = make_float4(0.f, 0.f, 0.f, 0.f);
    int j = beg;
    for (; j + 4 <= end; j += 4) {
        int s0 = g_esrc[j], s1 = g_esrc[j + 1], s2 = g_esrc[j + 2], s3 = g_esrc[j + 3];
        float4 v0 = t4[s0 * TX + f];
        float4 v1 = t4[s1 * TX + f];
        float4 v2 = t4[s2 * TX + f];
        float4 v3 = t4[s3 * TX + f];
        acc.x += (v0.x + v1.x) + (v2.x + v3.x);
        acc.y += (v0.y + v1.y) + (v2.y + v3.y);
        acc.z += (v0.z + v1.z) + (v2.z + v3.z);
        acc.w += (v0.w + v1.w) + (v2.w + v3.w);
    }
    for (; j < end; j++) {
        float4 v = t4[g_esrc[j] * TX + f];
        acc.x += v.x; acc.y += v.y; acc.z += v.z; acc.w += v.w;
    }
    float nd = g_norm_dst[n];
    float4 bb = ((const float4*)bias)[f];
    float4 o;
    o.x = fmaxf(fmaf(acc.x, nd, bb.x), 0.f);
    o.y = fmaxf(fmaf(acc.y, nd, bb.y), 0.f);
    o.z = fmaxf(fmaf(acc.z, nd, bb.z), 0.f);
    o.w = fmaxf(fmaf(acc.w, nd, bb.w), 0.f);
    ((float4*)out)[(size_t)n * TX + f] = o;
}

// ---------------- launch ----------------
extern "C" void kernel_launch(void* const* d_in, const int* in_sizes, int n_in,
                              void* d_out, int out_size) {
    const float* x  = (const float*)d_in[0];
    const int*   ed = (const int*)d_in[1];
    const float* W1 = (const float*)d_in[2];   const float* b1 = (const float*)d_in[3];
    const float* W2 = (const float*)d_in[4];   const float* b2 = (const float*)d_in[5];
    const float* W3 = (const float*)d_in[6];   const float* b3 = (const float*)d_in[7];
    const float* W4 = (const float*)d_in[8];   const float* b4 = (const float*)d_in[9];
    const float* W5 = (const float*)d_in[10];  const float* b5 = (const float*)d_in[11];

    const int Nn = in_sizes[0] / 128;
    const int E  = in_sizes[1] / 2;
    const int* src = ed;
    const int* dst = ed + E;

    void *pcs = nullptr, *pcd = nullptr, *pt = nullptr, *ph = nullptr;
    cudaGetSymbolAddress(&pcs, g_cnt_src);
    cudaGetSymbolAddress(&pcd, g_cnt_dst);
    cudaGetSymbolAddress(&pt,  g_t);
    cudaGetSymbolAddress(&ph,  g_h);
    float* t = (float*)pt;
    float* h = (float*)ph;

    cudaMemsetAsync(pcs, 0, Nn * sizeof(int), 0);
    cudaMemsetAsync(pcd, 0, Nn * sizeof(int), 0);

    int eb4 = (E / 4 + 255) / 256 + 1;    // 4 edges per thread
    degree_kernel<<<eb4, 256>>>(src, dst, E);
    scan_kernel<<<1, 1024>>>(Nn);
    bin_kernel<<<eb4, 256>>>(src, dst, E);

    // Layer 1: 128 -> 128
    gemm_kernel<128, 128><<<dim3((Nn + 127) / 128, 2), 256>>>(x, W1, t, Nn);
    gather_kernel<128><<<(Nn + 7) / 8, dim3(32, 8)>>>(t, b1, h, Nn);
    // Layer 2: 128 -> 64
    gemm_kernel<128, 64><<<dim3((Nn + 127) / 128, 1), 256>>>(h, W2, t, Nn);
    gather_kernel<64><<<(Nn + 15) / 16, dim3(16, 16)>>>(t, b2, h, Nn);
    // Layer 3: 64 -> 32
    gemm_kernel<64, 32><<<dim3((Nn + 127) / 128, 1), 256>>>(h, W3, t, Nn);
    gather_kernel<32><<<(Nn + 31) / 32, dim3(8, 32)>>>(t, b3, h, Nn);
    // Layer 4: 32 -> 16
    gemm_kernel<32, 16><<<dim3((Nn + 127) / 128, 1), 256>>>(h, W4, t, Nn);
    gather_kernel<16><<<(Nn + 63) / 64, dim3(4, 64)>>>(t, b4, h, Nn);
    // Layer 5: 16 -> 16
    gemm_kernel<16, 16><<<dim3((Nn + 127) / 128, 1), 256>>>(h, W5, t, Nn);
    gather_kernel<16><<<(Nn + 63) / 64, dim3(4, 64)>>>(t, b5, (float*)d_out, Nn);
}